// round 10
// baseline (speedup 1.0000x reference)
#include <cuda_runtime.h>
#include <cuda_fp16.h>
#include <cstdint>

#define BDIM 8192
#define INDIM 512
#define FDIM 64
#define ODIM 512
#define KDIM (INDIM * FDIM)   // 32768
#define NKC  INDIM            // 512 K-chunks of 64
#define EPSV 1e-3f

// Static device scratch (runtime allocation forbidden)
__device__ __align__(128) __half g_Wc[(size_t)ODIM * KDIM];   // 32 MB, W[o][k], k=i*64+f
__device__ __align__(128) float  g_xT[(size_t)INDIM * BDIM];  // 16 MB, x transposed [i][b]
__device__ float  g_biaseff[ODIM];

// ---------------------------------------------------------------------------
__device__ __forceinline__ uint32_t smem_u32(const void* p) {
    uint32_t a;
    asm("{ .reg .u64 t; cvta.to.shared.u64 t, %1; cvt.u32.u64 %0, t; }"
        : "=r"(a) : "l"(p));
    return a;
}

#define LDSM4(R, addr)                                                        \
    asm volatile("ldmatrix.sync.aligned.m8n8.x4.shared.b16 "                  \
                 "{%0,%1,%2,%3}, [%4];"                                       \
                 : "=r"((R)[0]), "=r"((R)[1]), "=r"((R)[2]), "=r"((R)[3])     \
                 : "r"(addr))

#define MMA16816(C, A, B0, B1)                                                \
    asm volatile("mma.sync.aligned.m16n8k16.row.col.f32.f16.f16.f32 "         \
                 "{%0,%1,%2,%3}, {%4,%5,%6,%7}, {%8,%9}, {%0,%1,%2,%3};"      \
                 : "+f"((C)[0]), "+f"((C)[1]), "+f"((C)[2]), "+f"((C)[3])     \
                 : "r"((A)[0]), "r"((A)[1]), "r"((A)[2]), "r"((A)[3]),        \
                   "r"(B0), "r"(B1))

#define CP_ASYNC16(dst, src)                                                  \
    asm volatile("cp.async.cg.shared.global [%0], [%1], 16;"                  \
                 :: "r"(dst), "l"(src) : "memory")

#define STS128(addr, v)                                                       \
    asm volatile("st.shared.v4.b32 [%0], {%1,%2,%3,%4};"                      \
                 :: "r"(addr), "r"((v)[0]), "r"((v)[1]), "r"((v)[2]),         \
                    "r"((v)[3]) : "memory")

// ---------------------------------------------------------------------------
// prep kernels (R9 versions — verified correct)
// ---------------------------------------------------------------------------
__global__ void prep_bias_kernel(const float* __restrict__ freqs,
                                 const float* __restrict__ phases,
                                 const float* __restrict__ beta,
                                 const float* __restrict__ lamb,
                                 const float* __restrict__ bias) {
    int o = blockIdx.x * blockDim.x + threadIdx.x;
    if (o >= ODIM) return;
    float sl0 = 0.f, sl1 = 0.f, sl2 = 0.f, sl3 = 0.f;
    float sl4 = 0.f, sl5 = 0.f, sl6 = 0.f, sl7 = 0.f;
#pragma unroll 1
    for (int i = 0; i < INDIM; i += 8) {
        sl0 += lamb[(size_t)(i + 0) * ODIM + o];
        sl1 += lamb[(size_t)(i + 1) * ODIM + o];
        sl2 += lamb[(size_t)(i + 2) * ODIM + o];
        sl3 += lamb[(size_t)(i + 3) * ODIM + o];
        sl4 += lamb[(size_t)(i + 4) * ODIM + o];
        sl5 += lamb[(size_t)(i + 5) * ODIM + o];
        sl6 += lamb[(size_t)(i + 6) * ODIM + o];
        sl7 += lamb[(size_t)(i + 7) * ODIM + o];
    }
    float sl = ((sl0 + sl1) + (sl2 + sl3)) + ((sl4 + sl5) + (sl6 + sl7));
    float sb = 0.f;
    for (int f = 0; f < FDIM; ++f) {
        float w = freqs[f], p = phases[f];
        float m   = expf(-0.5f * w * w) * sinf(p);
        float var = 0.5f - 0.5f * expf(-2.f * w * w) * cosf(2.f * p) - m * m;
        float s   = rsqrtf(EPSV + var);
        sb += m * s * beta[f * ODIM + o];
    }
    g_biaseff[o] = bias[o] - sl * sb;
}

__global__ void prep_xT_kernel(const float* __restrict__ x) {
    __shared__ float tile[32][33];
    int i0 = blockIdx.x * 32, b0 = blockIdx.y * 32;
    int tx = threadIdx.x, ty = threadIdx.y;
#pragma unroll
    for (int j = 0; j < 32; j += 8)
        tile[ty + j][tx] = x[(size_t)(b0 + ty + j) * INDIM + i0 + tx];
    __syncthreads();
#pragma unroll
    for (int j = 0; j < 32; j += 8)
        g_xT[(size_t)(i0 + ty + j) * BDIM + b0 + tx] = tile[tx][ty + j];
}

// W[o][i*64+f] = s_f * beta[f][o] * lamb[i][o]; coalesced: lane -> o.
__global__ void prep_wc_kernel(const float* __restrict__ freqs,
                               const float* __restrict__ phases,
                               const float* __restrict__ beta,
                               const float* __restrict__ lamb) {
    __shared__ float sS[FDIM];
    const int i = blockIdx.x;
    const int o = blockIdx.y * 256 + threadIdx.x;
    const int t = threadIdx.x;
    if (t < FDIM) {
        float w = freqs[t], p = phases[t];
        float m   = expf(-0.5f * w * w) * sinf(p);
        float var = 0.5f - 0.5f * expf(-2.f * w * w) * cosf(2.f * p) - m * m;
        sS[t] = rsqrtf(EPSV + var);
    }
    __syncthreads();
    const float lv = lamb[(size_t)i * ODIM + o];
    uint32_t h[32];
#pragma unroll
    for (int f2 = 0; f2 < 32; ++f2) {
        float v0 = sS[2 * f2]     * beta[(2 * f2) * ODIM + o]     * lv;
        float v1 = sS[2 * f2 + 1] * beta[(2 * f2 + 1) * ODIM + o] * lv;
        __half2 hh = __floats2half2_rn(v0, v1);
        h[f2] = *(uint32_t*)&hh;
    }
    uint4* dst = (uint4*)(g_Wc + (size_t)o * KDIM + (size_t)i * 64);
#pragma unroll
    for (int e = 0; e < 8; ++e) dst[e] = ((uint4*)h)[e];
}

// ---------------------------------------------------------------------------
// fused GEMM, 3-stage pipeline, 256 threads = 8 warps (2M x 4N), warp 64x64.
// FULL register double-buffering of ldmatrix fragments (af[2][4][4],
// bf[2][4][4]): k-step ks+1's 8 LDSM issue under ks's 32 MMAs.
// freqs/phases in shared float2 to stay under the 255-reg cliff.
// ---------------------------------------------------------------------------
#define SA_ST(s) ((uint32_t)(s) * 16384u)
#define SB_ST(s) (49152u + (uint32_t)(s) * 32768u)
#define SMEM_DYN (147456 + 1024)

__global__ void __launch_bounds__(256)
gemm_kernel(const float* __restrict__ freqs, const float* __restrict__ phases,
            float* __restrict__ out) {
    extern __shared__ char dynraw[];
    char* dyn = (char*)(((uintptr_t)dynraw + 1023) & ~(uintptr_t)1023);
    const uint32_t db = smem_u32(dyn);

    __shared__ float2 sWP[FDIM];

    const int tid  = threadIdx.x;
    const int lane = tid & 31;
    const int wid  = tid >> 5;
    const int wm   = wid >> 2;   // 0..1
    const int wn   = wid & 3;    // 0..3
    const int m_base = blockIdx.y * 128;
    const int n_base = blockIdx.x * 256;

    if (tid < FDIM) sWP[tid] = make_float2(freqs[tid], phases[tid]);
    __syncthreads();

    // --- A-generation mapping: thread owns 8 fixed f's x 4 rows ------------
    const int fg    = tid & 7;
    const int rbase = tid >> 3;
    const uint32_t gxm  = (uint32_t)(rbase & 7) << 4;
    const uint32_t gcol = ((uint32_t)fg * 16u) ^ gxm;
    const float* xsrc = g_xT + m_base + rbase;
    const float2* wp  = sWP + fg * 8;

    // --- B cp.async mapping: one o-row per thread, 8x16B -------------------
    const uint32_t cbase = (uint32_t)tid * 128u;
    const uint32_t cxm   = (uint32_t)(tid & 7) << 4;
    const __half* csrc = g_Wc + (size_t)(n_base + tid) * KDIM;

    // --- ldmatrix lane addressing ------------------------------------------
    const int arow = wm * 64 + (lane & 15);
    const uint32_t aoff = (uint32_t)arow * 128u;
    const uint32_t xmA  = (uint32_t)(arow & 7) << 4;
    const uint32_t kqa  = (uint32_t)(lane >> 4) * 16u;
    const int brow = wn * 64 + (lane & 7) + (lane >> 4) * 8;
    const uint32_t boff = (uint32_t)brow * 128u;
    const uint32_t xmB  = (uint32_t)(lane & 7) << 4;
    const uint32_t kqb  = (uint32_t)((lane >> 3) & 1) * 16u;

    float acc[4][8][4];
#pragma unroll
    for (int mi = 0; mi < 4; ++mi)
#pragma unroll
        for (int nj = 0; nj < 8; ++nj)
#pragma unroll
            for (int c = 0; c < 4; ++c) acc[mi][nj][c] = 0.f;

    auto gen_row = [&](int r, float xv, uint32_t st) {
        uint32_t h[4];
#pragma unroll
        for (int j = 0; j < 4; ++j) {
            float2 wp0 = wp[2 * j], wp1 = wp[2 * j + 1];
            float t0 = fmaf(wp0.x, xv, wp0.y);
            float t1 = fmaf(wp1.x, xv, wp1.y);
            t0 = fmaf(-6.2831853f, rintf(t0 * 0.15915494f), t0);
            t1 = fmaf(-6.2831853f, rintf(t1 * 0.15915494f), t1);
            __half2 hh = __floats2half2_rn(__sinf(t0), __sinf(t1));
            h[j] = *(uint32_t*)&hh;
        }
        STS128(db + st + ((uint32_t)(rbase + 32 * r)) * 128u + gcol, h);
    };

    auto issue_b = [&](int kc, uint32_t st) {
        const char* s = (const char*)(csrc + (size_t)kc * 64);
#pragma unroll
        for (int j = 0; j < 8; ++j)
            CP_ASYNC16(db + st + cbase + (((uint32_t)(j * 16)) ^ cxm),
                       s + j * 16);
        asm volatile("cp.async.commit_group;" ::: "memory");
    };

    // fragment double buffers (bf correctly sized for the 64-col warp tile)
    uint32_t af[2][4][4];
    uint32_t bf[2][4][4];
    auto load_frag = [&](int buf, int ks, uint32_t sa, uint32_t sb) {
#pragma unroll
        for (int mi = 0; mi < 4; ++mi)
            LDSM4(af[buf][mi], db + sa + aoff + (uint32_t)mi * 2048u +
                          (((uint32_t)(ks * 32) + kqa) ^ xmA));
#pragma unroll
        for (int nq = 0; nq < 4; ++nq)
            LDSM4(bf[buf][nq], db + sb + boff + (uint32_t)nq * 2048u +
                          (((uint32_t)(ks * 32) + kqb) ^ xmB));
    };

    // --- prologue: B0,B1 in flight; A0,A1 generated ---
    issue_b(0, SB_ST(0));
    issue_b(1, SB_ST(1));
#pragma unroll
    for (int r = 0; r < 4; ++r) gen_row(r, xsrc[32 * r], SA_ST(0));
#pragma unroll
    for (int r = 0; r < 4; ++r) gen_row(r, xsrc[(size_t)BDIM + 32 * r], SA_ST(1));

#pragma unroll 1
    for (int kc = 0; kc < NKC; ++kc) {
        const int st  = kc % 3;
        const uint32_t sa = SA_ST(st);
        const uint32_t sb = SB_ST(st);

        if (kc + 1 < NKC)
            asm volatile("cp.async.wait_group 1;" ::: "memory");
        else
            asm volatile("cp.async.wait_group 0;" ::: "memory");
        __syncthreads();

        const bool do_gen = (kc + 2 < NKC);
        const int  nst    = (kc + 2) % 3;
        float xv[4];
        if (do_gen) {
            issue_b(kc + 2, SB_ST(nst));
#pragma unroll
            for (int r = 0; r < 4; ++r)
                xv[r] = xsrc[(size_t)(kc + 2) * BDIM + 32 * r];
        }

        load_frag(0, 0, sa, sb);          // only exposed LDSM of the chunk

        // --- 4 k16 steps, fragments pipelined one step ahead ---
#pragma unroll
        for (int ks = 0; ks < 4; ++ks) {
            const int cur = ks & 1;
            if (ks < 3) load_frag(cur ^ 1, ks + 1, sa, sb);
#pragma unroll
            for (int mi = 0; mi < 4; ++mi)
#pragma unroll
                for (int nj = 0; nj < 8; ++nj)
                    MMA16816(acc[mi][nj], af[cur][mi],
                             bf[cur][nj >> 1][(nj & 1) * 2],
                             bf[cur][nj >> 1][(nj & 1) * 2 + 1]);
            if (do_gen)
                gen_row(ks, xv[ks], SA_ST(nst));   // MUFU/FMA/STS under HMMA
        }
    }

    // --- epilogue: acc + bias -> out ---
#pragma unroll
    for (int mi = 0; mi < 4; ++mi) {
        int row = m_base + wm * 64 + mi * 16 + (lane >> 2);
        float* o0 = out + (size_t)row * ODIM + n_base;
        float* o1 = o0 + (size_t)8 * ODIM;
#pragma unroll
        for (int nj = 0; nj < 8; ++nj) {
            int cl = wn * 64 + nj * 8 + (lane & 3) * 2;
            float b0 = __ldg(g_biaseff + n_base + cl);
            float b1 = __ldg(g_biaseff + n_base + cl + 1);
            float2 v0 = make_float2(acc[mi][nj][0] + b0, acc[mi][nj][1] + b1);
            float2 v1 = make_float2(acc[mi][nj][2] + b0, acc[mi][nj][3] + b1);
            *(float2*)(o0 + cl) = v0;
            *(float2*)(o1 + cl) = v1;
        }
    }
}

// ---------------------------------------------------------------------------
extern "C" void kernel_launch(void* const* d_in, const int* in_sizes, int n_in,
                              void* d_out, int out_size) {
    (void)in_sizes; (void)n_in; (void)out_size;
    const float* x      = (const float*)d_in[0];
    const float* freqs  = (const float*)d_in[1];
    const float* phases = (const float*)d_in[2];
    const float* beta   = (const float*)d_in[3];
    const float* lamb   = (const float*)d_in[4];
    const float* bias   = (const float*)d_in[5];
    float* out = (float*)d_out;

    cudaFuncSetAttribute(gemm_kernel,
                         cudaFuncAttributeMaxDynamicSharedMemorySize, SMEM_DYN);

    prep_bias_kernel<<<(ODIM + 255) / 256, 256>>>(freqs, phases, beta, lamb, bias);
    prep_xT_kernel<<<dim3(INDIM / 32, BDIM / 32), dim3(32, 8)>>>(x);
    prep_wc_kernel<<<dim3(INDIM, ODIM / 256), 256>>>(freqs, phases, beta, lamb);
    gemm_kernel<<<dim3(ODIM / 256, BDIM / 128), 256, SMEM_DYN>>>(freqs, phases, out);
}

// round 12
// speedup vs baseline: 1.0879x; 1.0879x over previous
#include <cuda_runtime.h>
#include <cuda_fp16.h>
#include <cstdint>

#define BDIM 8192
#define INDIM 512
#define FDIM 64
#define ODIM 512
#define KDIM (INDIM * FDIM)   // 32768
#define NKC  INDIM            // 512 K-chunks of 64
#define EPSV 1e-3f

// Static device scratch (runtime allocation forbidden)
__device__ __align__(128) __half g_Wc[(size_t)ODIM * KDIM];   // 32 MB  W[o][k]
__device__ __align__(128) __half g_A [(size_t)BDIM * KDIM];   // 512 MB A[b][k]
__device__ float  g_biaseff[ODIM];

// ---------------------------------------------------------------------------
__device__ __forceinline__ uint32_t smem_u32(const void* p) {
    uint32_t a;
    asm("{ .reg .u64 t; cvta.to.shared.u64 t, %1; cvt.u32.u64 %0, t; }"
        : "=r"(a) : "l"(p));
    return a;
}

#define LDSM4(R, addr)                                                        \
    asm volatile("ldmatrix.sync.aligned.m8n8.x4.shared.b16 "                  \
                 "{%0,%1,%2,%3}, [%4];"                                       \
                 : "=r"((R)[0]), "=r"((R)[1]), "=r"((R)[2]), "=r"((R)[3])     \
                 : "r"(addr))

#define MMA16816(C, A, B0, B1)                                                \
    asm volatile("mma.sync.aligned.m16n8k16.row.col.f32.f16.f16.f32 "         \
                 "{%0,%1,%2,%3}, {%4,%5,%6,%7}, {%8,%9}, {%0,%1,%2,%3};"      \
                 : "+f"((C)[0]), "+f"((C)[1]), "+f"((C)[2]), "+f"((C)[3])     \
                 : "r"((A)[0]), "r"((A)[1]), "r"((A)[2]), "r"((A)[3]),        \
                   "r"(B0), "r"(B1))

#define CP_ASYNC16(dst, src)                                                  \
    asm volatile("cp.async.cg.shared.global [%0], [%1], 16;"                  \
                 :: "r"(dst), "l"(src) : "memory")

// ---------------------------------------------------------------------------
// prep kernels
// ---------------------------------------------------------------------------
__global__ void prep_bias_kernel(const float* __restrict__ freqs,
                                 const float* __restrict__ phases,
                                 const float* __restrict__ beta,
                                 const float* __restrict__ lamb,
                                 const float* __restrict__ bias) {
    int o = blockIdx.x * blockDim.x + threadIdx.x;
    if (o >= ODIM) return;
    float sl0 = 0.f, sl1 = 0.f, sl2 = 0.f, sl3 = 0.f;
    float sl4 = 0.f, sl5 = 0.f, sl6 = 0.f, sl7 = 0.f;
#pragma unroll 1
    for (int i = 0; i < INDIM; i += 8) {
        sl0 += lamb[(size_t)(i + 0) * ODIM + o];
        sl1 += lamb[(size_t)(i + 1) * ODIM + o];
        sl2 += lamb[(size_t)(i + 2) * ODIM + o];
        sl3 += lamb[(size_t)(i + 3) * ODIM + o];
        sl4 += lamb[(size_t)(i + 4) * ODIM + o];
        sl5 += lamb[(size_t)(i + 5) * ODIM + o];
        sl6 += lamb[(size_t)(i + 6) * ODIM + o];
        sl7 += lamb[(size_t)(i + 7) * ODIM + o];
    }
    float sl = ((sl0 + sl1) + (sl2 + sl3)) + ((sl4 + sl5) + (sl6 + sl7));
    float sb = 0.f;
    for (int f = 0; f < FDIM; ++f) {
        float w = freqs[f], p = phases[f];
        float m   = expf(-0.5f * w * w) * sinf(p);
        float var = 0.5f - 0.5f * expf(-2.f * w * w) * cosf(2.f * p) - m * m;
        float s   = rsqrtf(EPSV + var);
        sb += m * s * beta[f * ODIM + o];
    }
    g_biaseff[o] = bias[o] - sl * sb;
}

// W[o][i*64+f] = s_f * beta[f][o] * lamb[i][o]; coalesced: lane -> o.
__global__ void prep_wc_kernel(const float* __restrict__ freqs,
                               const float* __restrict__ phases,
                               const float* __restrict__ beta,
                               const float* __restrict__ lamb) {
    __shared__ float sS[FDIM];
    const int i = blockIdx.x;
    const int o = blockIdx.y * 256 + threadIdx.x;
    const int t = threadIdx.x;
    if (t < FDIM) {
        float w = freqs[t], p = phases[t];
        float m   = expf(-0.5f * w * w) * sinf(p);
        float var = 0.5f - 0.5f * expf(-2.f * w * w) * cosf(2.f * p) - m * m;
        sS[t] = rsqrtf(EPSV + var);
    }
    __syncthreads();
    const float lv = lamb[(size_t)i * ODIM + o];
    uint32_t h[32];
#pragma unroll
    for (int f2 = 0; f2 < 32; ++f2) {
        float v0 = sS[2 * f2]     * beta[(2 * f2) * ODIM + o]     * lv;
        float v1 = sS[2 * f2 + 1] * beta[(2 * f2 + 1) * ODIM + o] * lv;
        __half2 hh = __floats2half2_rn(v0, v1);
        h[f2] = *(uint32_t*)&hh;
    }
    uint4* dst = (uint4*)(g_Wc + (size_t)o * KDIM + (size_t)i * 64);
#pragma unroll
    for (int e = 0; e < 8; ++e) dst[e] = ((uint4*)h)[e];
}

// A[b][i*64+f] = sin(w_f * x[b,i] + p_f) as fp16. One (b,i) per thread.
__global__ void sin_kernel(const float* __restrict__ x,
                           const float* __restrict__ freqs,
                           const float* __restrict__ phases) {
    __shared__ float2 sWP[FDIM];
    const int t = threadIdx.x;
    const int b = blockIdx.y;
    const int i = blockIdx.x * 256 + t;
    if (t < FDIM) sWP[t] = make_float2(freqs[t], phases[t]);
    __syncthreads();
    const float xv = x[(size_t)b * INDIM + i];
    uint32_t h[32];
#pragma unroll
    for (int j = 0; j < 32; ++j) {
        float2 wp0 = sWP[2 * j], wp1 = sWP[2 * j + 1];
        float t0 = fmaf(wp0.x, xv, wp0.y);
        float t1 = fmaf(wp1.x, xv, wp1.y);
        t0 = fmaf(-6.2831853f, rintf(t0 * 0.15915494f), t0);
        t1 = fmaf(-6.2831853f, rintf(t1 * 0.15915494f), t1);
        __half2 hh = __floats2half2_rn(__sinf(t0), __sinf(t1));
        h[j] = *(uint32_t*)&hh;
    }
    uint4* dst = (uint4*)(g_A + (size_t)b * KDIM + (size_t)i * 64);
#pragma unroll
    for (int e = 0; e < 8; ++e) dst[e] = ((uint4*)h)[e];
}

// ---------------------------------------------------------------------------
// pure GEMM: out = A @ Wc^T + bias.  CTA 128x256, 8 warps (2M x 4N), 64x64.
// 4-stage cp.async pipeline (A 16KB + B 32KB per stage), one commit per chunk,
// 3 chunks in flight; register double-buffered ldmatrix fragments.
// ---------------------------------------------------------------------------
#define SA_ST(s) ((uint32_t)(s) * 16384u)
#define SB_ST(s) (65536u + (uint32_t)(s) * 32768u)
#define SMEM_DYN (196608 + 1024)

__global__ void __launch_bounds__(256)
gemm_kernel(float* __restrict__ out) {
    extern __shared__ char dynraw[];
    char* dyn = (char*)(((uintptr_t)dynraw + 1023) & ~(uintptr_t)1023);
    const uint32_t db = smem_u32(dyn);

    const int tid  = threadIdx.x;
    const int lane = tid & 31;
    const int wid  = tid >> 5;
    const int wm   = wid >> 2;   // 0..1
    const int wn   = wid & 3;    // 0..3
    const int m_base = blockIdx.y * 128;
    const int n_base = blockIdx.x * 256;

    // --- A cp.async mapping: 2 threads per row, 64B each -------------------
    const int arow_c = tid >> 1;          // 0..127
    const int ahalf  = tid & 1;
    const uint32_t abase_sm = (uint32_t)arow_c * 128u;
    const uint32_t axm      = (uint32_t)(arow_c & 7) << 4;
    const __half* asrc = g_A + (size_t)(m_base + arow_c) * KDIM + ahalf * 32;

    // --- B cp.async mapping: one o-row per thread, 8x16B -------------------
    const uint32_t bbase_sm = (uint32_t)tid * 128u;
    const uint32_t bxm      = (uint32_t)(tid & 7) << 4;
    const __half* bsrc = g_Wc + (size_t)(n_base + tid) * KDIM;

    // --- ldmatrix lane addressing ------------------------------------------
    const int arow = wm * 64 + (lane & 15);
    const uint32_t aoff = (uint32_t)arow * 128u;
    const uint32_t xmA  = (uint32_t)(arow & 7) << 4;
    const uint32_t kqa  = (uint32_t)(lane >> 4) * 16u;
    const int brow = wn * 64 + (lane & 7) + (lane >> 4) * 8;
    const uint32_t boff = (uint32_t)brow * 128u;
    const uint32_t xmB  = (uint32_t)(lane & 7) << 4;
    const uint32_t kqb  = (uint32_t)((lane >> 3) & 1) * 16u;

    float acc[4][8][4];
#pragma unroll
    for (int mi = 0; mi < 4; ++mi)
#pragma unroll
        for (int nj = 0; nj < 8; ++nj)
#pragma unroll
            for (int c = 0; c < 4; ++c) acc[mi][nj][c] = 0.f;

    auto issue = [&](int kc) {
        const uint32_t st = (uint32_t)(kc & 3);
        const char* sa = (const char*)(asrc + (size_t)kc * 64);
#pragma unroll
        for (int j = 0; j < 4; ++j)
            CP_ASYNC16(db + SA_ST(st) + abase_sm +
                           (((uint32_t)(ahalf * 64 + j * 16)) ^ axm),
                       sa + j * 16);
        const char* sb = (const char*)(bsrc + (size_t)kc * 64);
#pragma unroll
        for (int j = 0; j < 8; ++j)
            CP_ASYNC16(db + SB_ST(st) + bbase_sm + (((uint32_t)(j * 16)) ^ bxm),
                       sb + j * 16);
        asm volatile("cp.async.commit_group;" ::: "memory");
    };

    uint32_t af[2][4][4];
    uint32_t bf[2][4][4];
    auto load_frag = [&](int buf, int ks, uint32_t sa, uint32_t sb) {
#pragma unroll
        for (int mi = 0; mi < 4; ++mi)
            LDSM4(af[buf][mi], db + sa + aoff + (uint32_t)mi * 2048u +
                          (((uint32_t)(ks * 32) + kqa) ^ xmA));
#pragma unroll
        for (int nq = 0; nq < 4; ++nq)
            LDSM4(bf[buf][nq], db + sb + boff + (uint32_t)nq * 2048u +
                          (((uint32_t)(ks * 32) + kqb) ^ xmB));
    };

    // --- prologue: chunks 0,1,2 in flight ---
    issue(0);
    issue(1);
    issue(2);

#pragma unroll 1
    for (int kc = 0; kc < NKC; ++kc) {
        const uint32_t sa = SA_ST((uint32_t)(kc & 3));
        const uint32_t sb = SB_ST((uint32_t)(kc & 3));

        // wait until chunk kc's group is complete (exact tail peeling)
        if (kc < NKC - 2)
            asm volatile("cp.async.wait_group 2;" ::: "memory");
        else if (kc == NKC - 2)
            asm volatile("cp.async.wait_group 1;" ::: "memory");
        else
            asm volatile("cp.async.wait_group 0;" ::: "memory");
        __syncthreads();

        if (kc + 3 < NKC) issue(kc + 3);

        load_frag(0, 0, sa, sb);          // only exposed LDSM of the chunk

#pragma unroll
        for (int ks = 0; ks < 4; ++ks) {
            const int cur = ks & 1;
            if (ks < 3) load_frag(cur ^ 1, ks + 1, sa, sb);
#pragma unroll
            for (int mi = 0; mi < 4; ++mi)
#pragma unroll
                for (int nj = 0; nj < 8; ++nj)
                    MMA16816(acc[mi][nj], af[cur][mi],
                             bf[cur][nj >> 1][(nj & 1) * 2],
                             bf[cur][nj >> 1][(nj & 1) * 2 + 1]);
        }
    }

    // --- epilogue: acc + bias -> out ---
#pragma unroll
    for (int mi = 0; mi < 4; ++mi) {
        int row = m_base + wm * 64 + mi * 16 + (lane >> 2);
        float* o0 = out + (size_t)row * ODIM + n_base;
        float* o1 = o0 + (size_t)8 * ODIM;
#pragma unroll
        for (int nj = 0; nj < 8; ++nj) {
            int cl = wn * 64 + nj * 8 + (lane & 3) * 2;
            float b0 = __ldg(g_biaseff + n_base + cl);
            float b1 = __ldg(g_biaseff + n_base + cl + 1);
            float2 v0 = make_float2(acc[mi][nj][0] + b0, acc[mi][nj][1] + b1);
            float2 v1 = make_float2(acc[mi][nj][2] + b0, acc[mi][nj][3] + b1);
            *(float2*)(o0 + cl) = v0;
            *(float2*)(o1 + cl) = v1;
        }
    }
}

// ---------------------------------------------------------------------------
extern "C" void kernel_launch(void* const* d_in, const int* in_sizes, int n_in,
                              void* d_out, int out_size) {
    (void)in_sizes; (void)n_in; (void)out_size;
    const float* x      = (const float*)d_in[0];
    const float* freqs  = (const float*)d_in[1];
    const float* phases = (const float*)d_in[2];
    const float* beta   = (const float*)d_in[3];
    const float* lamb   = (const float*)d_in[4];
    const float* bias   = (const float*)d_in[5];
    float* out = (float*)d_out;

    cudaFuncSetAttribute(gemm_kernel,
                         cudaFuncAttributeMaxDynamicSharedMemorySize, SMEM_DYN);

    prep_bias_kernel<<<(ODIM + 255) / 256, 256>>>(freqs, phases, beta, lamb, bias);
    prep_wc_kernel<<<dim3(INDIM, ODIM / 256), 256>>>(freqs, phases, beta, lamb);
    sin_kernel<<<dim3(INDIM / 256, BDIM), 256>>>(x, freqs, phases);
    gemm_kernel<<<dim3(ODIM / 256, BDIM / 128), 256, SMEM_DYN>>>(out);
}